// round 1
// baseline (speedup 1.0000x reference)
#include <cuda_runtime.h>
#include <cstdint>

// MaxUnpooling2D: updates [16,64,64,256] f32, mask [16,64,64,256] i32
// (flat index over (oH=128, oW=128, C=256), guaranteed inside the cell's
// own 2x2 window). Output [16,128,128,256] f32.
//
// Strategy: one thread per input float4 (4 channels). Each thread writes all
// four 2x2-window output positions for its 4 channels: the mask-selected
// position gets the update value, the others get 0. Windows are disjoint
// across input cells, so this covers the whole output exactly once with no
// atomics and no zero-init pass.

static constexpr int B = 16, H = 64, W = 64, C = 256;
static constexpr int oW = 128;
static constexpr int C4 = C / 4;              // float4 per (b,h,w) row = 64
static constexpr int N4 = B * H * W * C4;     // total threads = 4,194,304

__global__ void __launch_bounds__(256)
maxunpool_kernel(const float4* __restrict__ upd,
                 const int4*  __restrict__ msk,
                 float4* __restrict__ out)
{
    int t = blockIdx.x * blockDim.x + threadIdx.x;
    if (t >= N4) return;

    // decompose t -> (b, h, w, c4); all dims are powers of two
    int c4 = t & (C4 - 1);
    int w  = (t >> 6) & (W - 1);
    int h  = (t >> 12) & (H - 1);
    int b  = t >> 18;

    float4 u = upd[t];
    int4   m = msk[t];

    // sel = dy*2 + dx, where dy = (m >> 15) & 1, dx = (m >> 8) & 1
    int s0 = ((m.x >> 14) & 2) | ((m.x >> 8) & 1);
    int s1 = ((m.y >> 14) & 2) | ((m.y >> 8) & 1);
    int s2 = ((m.z >> 14) & 2) | ((m.z >> 8) & 1);
    int s3 = ((m.w >> 14) & 2) | ((m.w >> 8) & 1);

    // output base in float4 units: ((b*128 + 2h)*128 + 2w)*64 + c4
    int base = (((b << 7) + (h << 1)) << 7 | (w << 1)) * C4 + c4;
    // strides (float4 units): dx -> +C4 (=64), dy -> +oW*C4 (=8192)

#pragma unroll
    for (int p = 0; p < 4; ++p) {
        float4 v;
        v.x = (s0 == p) ? u.x : 0.0f;
        v.y = (s1 == p) ? u.y : 0.0f;
        v.z = (s2 == p) ? u.z : 0.0f;
        v.w = (s3 == p) ? u.w : 0.0f;
        out[base + (p >> 1) * (oW * C4) + (p & 1) * C4] = v;
    }
}

extern "C" void kernel_launch(void* const* d_in, const int* in_sizes, int n_in,
                              void* d_out, int out_size)
{
    const float4* upd = (const float4*)d_in[0];
    const int4*   msk = (const int4*)d_in[1];
    float4*       out = (float4*)d_out;

    const int threads = 256;
    const int blocks = N4 / threads;  // 16384, exact
    maxunpool_kernel<<<blocks, threads>>>(upd, msk, out);
}